// round 7
// baseline (speedup 1.0000x reference)
#include <cuda_runtime.h>

#define NPTS 2048
#define KCAP 256
#define NTHREADS 256
#define WARPS_PER_ROW 8
#define STAGE_CAP 256   // provably sufficient: entries with idx>=256 map past KCAP
#define CUT2 0.09f

// d_out layout (float32):
//   [0, N*K)            neighbours (N,K)
//   [N*K, N*K*4)        cell_indices (N,K,3)
//   [N*K*4]             actual_max
#define MAX_OFFSET ((size_t)NPTS * KCAP * 4)

// SoA position scratch (allocation-free: __device__ globals)
__device__ float g_px[NPTS];
__device__ float g_py[NPTS];
__device__ float g_pz[NPTS];

__global__ void pb_pack_kernel(const float* __restrict__ pos, float* __restrict__ out_max) {
    const int j = blockIdx.x * blockDim.x + threadIdx.x;
    if (j < NPTS) {
        g_px[j] = pos[3 * j];
        g_py[j] = pos[3 * j + 1];
        g_pz[j] = pos[3 * j + 2];
    }
    if (j == 0) *out_max = 0.0f;
}

__global__ __launch_bounds__(NTHREADS)
void pb_nbr_kernel(float* __restrict__ out) {
    __shared__ int stage[WARPS_PER_ROW][STAGE_CAP];   // 8 KB
    __shared__ int scount[WARPS_PER_ROW];

    const int tid  = threadIdx.x;
    const int lane = tid & 31;
    const int q    = tid >> 5;            // eighth of this row's ordered work
    const unsigned lmask = (1u << lane) - 1u;

    const int i = blockIdx.x;             // one row per block
    const float pix = __ldg(&g_px[i]);
    const float piy = __ldg(&g_py[i]);
    const float piz = __ldg(&g_pz[i]);

    // Per-dimension shift feasibility (margin 1e-4 >> fp32 rounding).
    const bool okx[3] = { pix < 0.30001f, true, pix > 0.69999f };
    const bool oky[3] = { piy < 0.30001f, true, piy > 0.69999f };
    const bool okz[3] = { piz < 0.30001f, true, piz > 0.69999f };

    // Active cells -> ordered chunk count T = nA*64; each warp takes T/8 chunks.
    int nA = 0;
#pragma unroll
    for (int c = 0; c < 27; c++) {
        const int sx = (c % 3) - 1, sy = ((c / 3) % 3) - 1, sz = (c / 9) - 1;
        if (okx[sx + 1] && oky[sy + 1] && okz[sz + 1]) nA++;
    }
    const int per = nA * (64 / WARPS_PER_ROW);
    const int t0 = q * per;
    const int t1 = t0 + per;

    int* __restrict__ mystage = stage[q];
    int scnt = 0;                  // uniform in warp
    int tbase = 0;

    for (int c = 0; c < 27; c++) {
        const int sx = (c % 3) - 1, sy = ((c / 3) % 3) - 1, sz = (c / 9) - 1;
        if (!(okx[sx + 1] && oky[sy + 1] && okz[sz + 1])) continue;

        const int lo = (t0 > tbase) ? t0 : tbase;
        const int hi = (t1 < tbase + 64) ? t1 : tbase + 64;
        if (lo < hi) {
            const float fsx = (float)sx, fsy = (float)sy, fsz = (float)sz;
            const bool selfc = (c == 13);
            for (int t = lo; t < hi; t++) {
                const int j = ((t - tbase) << 5) + lane;
                const float x = __ldg(&g_px[j]);
                const float y = __ldg(&g_py[j]);
                const float z = __ldg(&g_pz[j]);
                // Exact reference rounding: ((p_j + s) - p_i), plain mul/add, no FMA.
                const float dx = __fadd_rn(__fadd_rn(x, fsx), -pix);
                const float dy = __fadd_rn(__fadd_rn(y, fsy), -piy);
                const float dz = __fadd_rn(__fadd_rn(z, fsz), -piz);
                const float d2 = __fadd_rn(__fadd_rn(__fmul_rn(dx, dx), __fmul_rn(dy, dy)),
                                           __fmul_rn(dz, dz));
                const bool hit = (d2 <= CUT2) && !(selfc && (j == i));

                const unsigned b = __ballot_sync(0xFFFFFFFFu, hit);
                if (b) {
                    if (hit) {
                        const int idx = scnt + __popc(b & lmask);
                        if (idx < STAGE_CAP) mystage[idx] = (c << 11) | j;
                    }
                    scnt += __popc(b);
                }
            }
        }
        tbase += 64;
    }

    if (lane == 0) scount[q] = scnt;
    __syncthreads();

    int base = 0, rowTotal = 0;
#pragma unroll
    for (int q2 = 0; q2 < WARPS_PER_ROW; q2++) {
        const int cc = scount[q2];
        if (q2 < q) base += cc;
        rowTotal += cc;
    }

    float* __restrict__ out_neigh = out + (size_t)i * KCAP;
    float* __restrict__ out_cells = out + (size_t)NPTS * KCAP + (size_t)i * KCAP * 3;

    // Copy this warp's in-order staged segment to its prefix position.
    const int nwrite = (scnt < STAGE_CAP) ? scnt : STAGE_CAP;
    for (int e = lane; e < nwrite; e += 32) {
        const int off = base + e;
        if (off < KCAP) {
            const int code = mystage[e];
            const int j = code & 2047;
            const int c = code >> 11;
            out_neigh[off]         = (float)j;
            out_cells[3 * off]     = (float)((c % 3) - 1);
            out_cells[3 * off + 1] = (float)(((c / 3) % 3) - 1);
            out_cells[3 * off + 2] = (float)((c / 9) - 1);
        }
    }

    // Tail fill by all 256 threads: neighbours=-1, cells=(1,1,1)
    const int filled = (rowTotal < KCAP) ? rowTotal : KCAP;
    for (int k = filled + tid; k < KCAP; k += NTHREADS) {
        out_neigh[k]         = -1.0f;
        out_cells[3 * k]     = 1.0f;
        out_cells[3 * k + 1] = 1.0f;
        out_cells[3 * k + 2] = 1.0f;
    }
    if (tid == 0) {
        atomicMax((int*)(out + MAX_OFFSET), __float_as_int((float)rowTotal));
    }
}

extern "C" void kernel_launch(void* const* d_in, const int* in_sizes, int n_in,
                              void* d_out, int out_size) {
    const float* pos = (const float*)d_in[0];
    float* out = (float*)d_out;
    pb_pack_kernel<<<(NPTS + 255) / 256, 256>>>(pos, out + MAX_OFFSET);
    pb_nbr_kernel<<<NPTS, NTHREADS>>>(out);
}